// round 1
// baseline (speedup 1.0000x reference)
#include <cuda_runtime.h>
#include <math.h>

#define Bn  2
#define Tn  2048
#define Dn  1024
#define Hn  16
#define HDn 64
#define Mn  (Bn * Tn)   // 4096

// -------- scratch (static device globals; no allocations allowed) --------
__device__ float g_Q[(size_t)Bn * Hn * Tn * HDn];   // [B,H,T,64]
__device__ float g_K[(size_t)Bn * Hn * Tn * HDn];
__device__ float g_V[(size_t)Bn * Hn * Tn * HDn];
__device__ float g_O[(size_t)Mn * Dn];              // [B*T, D] (heads re-concat)
__device__ float g_P[(size_t)Mn * Dn];              // pre-LN = O@Wo + bo + x

// =========================================================================
// SGEMM 128x128x8, 256 threads, 8x8 per-thread microtile.
// mode 0: out = A@W + bias, scattered to [B,H,T,64]  (QKV projections)
// mode 1: out = A@W + bias + resid, row-major [M,D]  (output projection)
// =========================================================================
__global__ void __launch_bounds__(256) sgemm128(
    const float* __restrict__ A,      // [M, 1024]
    const float* __restrict__ W,      // [1024, 1024]
    const float* __restrict__ bias,   // [1024]
    const float* __restrict__ resid,  // [M, 1024] or nullptr
    float* __restrict__ out,
    int mode)
{
    __shared__ float As[8][128];
    __shared__ float Bs[8][128];

    const int tid = threadIdx.x;
    const int tx = tid & 15;          // column group
    const int ty = tid >> 4;          // row group
    const int m0 = blockIdx.y * 128;
    const int n0 = blockIdx.x * 128;

    const int arow = tid >> 1;        // 0..127
    const int acol = (tid & 1) * 4;   // 0 or 4
    const int brow = tid >> 5;        // 0..7
    const int bcol = (tid & 31) * 4;  // 0..124

    const float* Aptr = A + (size_t)(m0 + arow) * Dn + acol;
    const float* Wptr = W + (size_t)brow * Dn + n0 + bcol;

    float acc[8][8];
#pragma unroll
    for (int i = 0; i < 8; i++)
#pragma unroll
        for (int j = 0; j < 8; j++) acc[i][j] = 0.f;

    for (int k0 = 0; k0 < Dn; k0 += 8) {
        float4 av = *(const float4*)(Aptr + k0);
        As[acol + 0][arow] = av.x;
        As[acol + 1][arow] = av.y;
        As[acol + 2][arow] = av.z;
        As[acol + 3][arow] = av.w;
        float4 bv = *(const float4*)(Wptr + (size_t)k0 * Dn);
        *(float4*)&Bs[brow][bcol] = bv;
        __syncthreads();
#pragma unroll
        for (int kk = 0; kk < 8; kk++) {
            float af[8], bf[8];
            *(float4*)&af[0] = *(const float4*)&As[kk][ty * 8];
            *(float4*)&af[4] = *(const float4*)&As[kk][ty * 8 + 4];
            *(float4*)&bf[0] = *(const float4*)&Bs[kk][tx * 8];
            *(float4*)&bf[4] = *(const float4*)&Bs[kk][tx * 8 + 4];
#pragma unroll
            for (int i = 0; i < 8; i++)
#pragma unroll
                for (int j = 0; j < 8; j++)
                    acc[i][j] += af[i] * bf[j];
        }
        __syncthreads();
    }

    if (mode == 0) {
        // scatter to [B, H, T, 64] (+bias)
#pragma unroll
        for (int i = 0; i < 8; i++) {
            int m = m0 + ty * 8 + i;
            int bb = m >> 11;             // / Tn
            int t  = m & (Tn - 1);
#pragma unroll
            for (int j4 = 0; j4 < 8; j4 += 4) {
                int n  = n0 + tx * 8 + j4;
                int h  = n >> 6;
                int hd = n & 63;
                float4 r;
                r.x = acc[i][j4 + 0] + bias[n + 0];
                r.y = acc[i][j4 + 1] + bias[n + 1];
                r.z = acc[i][j4 + 2] + bias[n + 2];
                r.w = acc[i][j4 + 3] + bias[n + 3];
                *(float4*)&out[((((size_t)bb * Hn + h) * Tn) + t) * HDn + hd] = r;
            }
        }
    } else {
        // row-major (+bias +residual)
#pragma unroll
        for (int i = 0; i < 8; i++) {
            int m = m0 + ty * 8 + i;
#pragma unroll
            for (int j4 = 0; j4 < 8; j4 += 4) {
                int n = n0 + tx * 8 + j4;
                size_t off = (size_t)m * Dn + n;
                float4 rv = *(const float4*)&resid[off];
                float4 r;
                r.x = acc[i][j4 + 0] + bias[n + 0] + rv.x;
                r.y = acc[i][j4 + 1] + bias[n + 1] + rv.y;
                r.z = acc[i][j4 + 2] + bias[n + 2] + rv.z;
                r.w = acc[i][j4 + 3] + bias[n + 3] + rv.w;
                *(float4*)&out[off] = r;
            }
        }
    }
}

// =========================================================================
// Flash attention: 1 CTA per (b,h, 64-query tile). 256 threads.
// Q/K stored d-major (transposed) in smem with pad 65; V natural; P [i][j].
// Online softmax, O accumulated in registers (4x4 per thread).
// Dynamic smem: (2*64*65 + 2*64*64) * 4 = 66048 bytes.
// =========================================================================
#define ATTN_SMEM_BYTES ((2 * 64 * 65 + 2 * 64 * 64) * 4)

__global__ void __launch_bounds__(256) attn64(
    const float* __restrict__ gQ,   // [B*H, T, 64]
    const float* __restrict__ gK,
    const float* __restrict__ gV,
    float* __restrict__ gO)         // [B*T, 1024]
{
    extern __shared__ float sm[];
    float* Qs = sm;                 // [64][65]  Qs[d][i]
    float* Ks = sm + 64 * 65;       // [64][65]  Ks[d][j]
    float* Vs = sm + 2 * 64 * 65;   // [64][64]  Vs[j][d]
    float* Ps = Vs + 64 * 64;       // [64][64]  Ps[i][j]

    const int tid = threadIdx.x;
    const int tx = tid & 15;        // j / d column group
    const int ty = tid >> 4;        // i row group
    const int bh = blockIdx.y;      // 0..31
    const int q0 = blockIdx.x << 6; // query tile base
    const int b = bh >> 4;
    const int h = bh & 15;

    const float* Q = gQ + ((size_t)bh * Tn + q0) * HDn;
    const float* K = gK + (size_t)bh * Tn * HDn;
    const float* V = gV + (size_t)bh * Tn * HDn;

    // load Q tile transposed, fold 1/sqrt(64)
    for (int idx = tid; idx < 64 * 16; idx += 256) {
        int r  = idx >> 4;
        int c4 = (idx & 15) << 2;
        float4 v = *(const float4*)&Q[r * 64 + c4];
        Qs[(c4 + 0) * 65 + r] = v.x * 0.125f;
        Qs[(c4 + 1) * 65 + r] = v.y * 0.125f;
        Qs[(c4 + 2) * 65 + r] = v.z * 0.125f;
        Qs[(c4 + 3) * 65 + r] = v.w * 0.125f;
    }

    float m_i[4], l_i[4], o_acc[4][4];
#pragma unroll
    for (int i = 0; i < 4; i++) {
        m_i[i] = -1e30f;
        l_i[i] = 0.f;
#pragma unroll
        for (int j = 0; j < 4; j++) o_acc[i][j] = 0.f;
    }

    for (int kt = 0; kt < Tn; kt += 64) {
        // load K tile transposed + V tile natural
        for (int idx = tid; idx < 64 * 16; idx += 256) {
            int r  = idx >> 4;
            int c4 = (idx & 15) << 2;
            float4 v = *(const float4*)&K[(kt + r) * 64 + c4];
            Ks[(c4 + 0) * 65 + r] = v.x;
            Ks[(c4 + 1) * 65 + r] = v.y;
            Ks[(c4 + 2) * 65 + r] = v.z;
            Ks[(c4 + 3) * 65 + r] = v.w;
            *(float4*)&Vs[r * 64 + c4] = *(const float4*)&V[(kt + r) * 64 + c4];
        }
        __syncthreads();

        // S = (Q/8) K^T  -> 4x4 per thread
        float s[4][4];
#pragma unroll
        for (int i = 0; i < 4; i++)
#pragma unroll
            for (int j = 0; j < 4; j++) s[i][j] = 0.f;

#pragma unroll 8
        for (int d = 0; d < 64; d++) {
            float qf[4], kf[4];
#pragma unroll
            for (int i = 0; i < 4; i++) qf[i] = Qs[d * 65 + ty * 4 + i];
#pragma unroll
            for (int j = 0; j < 4; j++) kf[j] = Ks[d * 65 + tx * 4 + j];
#pragma unroll
            for (int i = 0; i < 4; i++)
#pragma unroll
                for (int j = 0; j < 4; j++)
                    s[i][j] += qf[i] * kf[j];
        }

        // online softmax (row stats shared across the 16-lane tx group)
        float corr[4];
#pragma unroll
        for (int i = 0; i < 4; i++) {
            float mx = fmaxf(fmaxf(s[i][0], s[i][1]), fmaxf(s[i][2], s[i][3]));
#pragma unroll
            for (int off = 1; off < 16; off <<= 1)
                mx = fmaxf(mx, __shfl_xor_sync(0xffffffffu, mx, off));
            float mnew = fmaxf(m_i[i], mx);
            corr[i] = __expf(m_i[i] - mnew);
            m_i[i] = mnew;
            float sum = 0.f;
#pragma unroll
            for (int j = 0; j < 4; j++) {
                float p = __expf(s[i][j] - mnew);
                s[i][j] = p;
                sum += p;
            }
#pragma unroll
            for (int off = 1; off < 16; off <<= 1)
                sum += __shfl_xor_sync(0xffffffffu, sum, off);
            l_i[i] = l_i[i] * corr[i] + sum;
        }

        // write P tile
#pragma unroll
        for (int i = 0; i < 4; i++) {
            float4 pv = make_float4(s[i][0], s[i][1], s[i][2], s[i][3]);
            *(float4*)&Ps[(ty * 4 + i) * 64 + tx * 4] = pv;
        }
        __syncthreads();

        // O = O*corr + P@V
#pragma unroll
        for (int i = 0; i < 4; i++)
#pragma unroll
            for (int j = 0; j < 4; j++) o_acc[i][j] *= corr[i];

#pragma unroll 4
        for (int j = 0; j < 64; j++) {
            float4 vv = *(const float4*)&Vs[j * 64 + tx * 4];
#pragma unroll
            for (int i = 0; i < 4; i++) {
                float p = Ps[(ty * 4 + i) * 64 + j];
                o_acc[i][0] += p * vv.x;
                o_acc[i][1] += p * vv.y;
                o_acc[i][2] += p * vv.z;
                o_acc[i][3] += p * vv.w;
            }
        }
        __syncthreads();   // protect Ks/Vs/Ps before next tile's writes
    }

    // normalize + store to [B*T, D] with column h*64 + d
#pragma unroll
    for (int i = 0; i < 4; i++) {
        int grow = b * Tn + q0 + ty * 4 + i;
        float inv = 1.0f / l_i[i];
        float4 r = make_float4(o_acc[i][0] * inv, o_acc[i][1] * inv,
                               o_acc[i][2] * inv, o_acc[i][3] * inv);
        *(float4*)&gO[(size_t)grow * Dn + h * HDn + tx * 4] = r;
    }
}

// =========================================================================
// LayerNorm: 1 block per row (4096 rows), 256 threads, 1 float4 per thread.
// =========================================================================
__global__ void __launch_bounds__(256) ln_kernel(
    const float* __restrict__ P,
    const float* __restrict__ gw,
    const float* __restrict__ gb,
    float* __restrict__ out)
{
    const int row = blockIdx.x;
    const int tid = threadIdx.x;
    const float4 v = ((const float4*)(P + (size_t)row * Dn))[tid];

    float s  = v.x + v.y + v.z + v.w;
    float ss = v.x * v.x + v.y * v.y + v.z * v.z + v.w * v.w;
#pragma unroll
    for (int off = 16; off; off >>= 1) {
        s  += __shfl_xor_sync(0xffffffffu, s, off);
        ss += __shfl_xor_sync(0xffffffffu, ss, off);
    }
    __shared__ float sh_s[8], sh_ss[8];
    const int w = tid >> 5, lane = tid & 31;
    if (lane == 0) { sh_s[w] = s; sh_ss[w] = ss; }
    __syncthreads();
    if (w == 0) {
        float s2  = (lane < 8) ? sh_s[lane]  : 0.f;
        float ss2 = (lane < 8) ? sh_ss[lane] : 0.f;
#pragma unroll
        for (int off = 4; off; off >>= 1) {
            s2  += __shfl_xor_sync(0xffffffffu, s2, off);
            ss2 += __shfl_xor_sync(0xffffffffu, ss2, off);
        }
        if (lane == 0) { sh_s[0] = s2; sh_ss[0] = ss2; }
    }
    __syncthreads();

    const float mu  = sh_s[0] * (1.0f / Dn);
    const float var = sh_ss[0] * (1.0f / Dn) - mu * mu;
    const float rs  = rsqrtf(var + 1e-5f);

    const float4 g = ((const float4*)gw)[tid];
    const float4 bb = ((const float4*)gb)[tid];
    float4 r;
    r.x = (v.x - mu) * rs * g.x + bb.x;
    r.y = (v.y - mu) * rs * g.y + bb.y;
    r.z = (v.z - mu) * rs * g.z + bb.z;
    r.w = (v.w - mu) * rs * g.w + bb.w;
    ((float4*)(out + (size_t)row * Dn))[tid] = r;
}

// =========================================================================
extern "C" void kernel_launch(void* const* d_in, const int* in_sizes, int n_in,
                              void* d_out, int out_size)
{
    const float* x  = (const float*)d_in[0];
    const float* Wq = (const float*)d_in[1];
    const float* bq = (const float*)d_in[2];
    const float* Wk = (const float*)d_in[3];
    const float* bk = (const float*)d_in[4];
    const float* Wv = (const float*)d_in[5];
    const float* bv = (const float*)d_in[6];
    const float* Wo = (const float*)d_in[7];
    const float* bo = (const float*)d_in[8];
    const float* lg = (const float*)d_in[9];
    const float* lb = (const float*)d_in[10];
    float* out = (float*)d_out;

    float *gQ, *gK, *gV, *gO, *gP;
    cudaGetSymbolAddress((void**)&gQ, g_Q);
    cudaGetSymbolAddress((void**)&gK, g_K);
    cudaGetSymbolAddress((void**)&gV, g_V);
    cudaGetSymbolAddress((void**)&gO, g_O);
    cudaGetSymbolAddress((void**)&gP, g_P);

    cudaFuncSetAttribute(attn64, cudaFuncAttributeMaxDynamicSharedMemorySize,
                         ATTN_SMEM_BYTES);

    dim3 gproj(Dn / 128, Mn / 128);   // (8, 32)
    sgemm128<<<gproj, 256>>>(x, Wq, bq, nullptr, gQ, 0);
    sgemm128<<<gproj, 256>>>(x, Wk, bk, nullptr, gK, 0);
    sgemm128<<<gproj, 256>>>(x, Wv, bv, nullptr, gV, 0);

    attn64<<<dim3(Tn / 64, Bn * Hn), 256, ATTN_SMEM_BYTES>>>(gQ, gK, gV, gO);

    sgemm128<<<gproj, 256>>>(gO, Wo, bo, x, gP, 1);

    ln_kernel<<<Mn, 256>>>(gP, lg, lb, out);
}

// round 2
// speedup vs baseline: 1.6765x; 1.6765x over previous
#include <cuda_runtime.h>
#include <math.h>
#include <stdint.h>

#define Bn  2
#define Tn  2048
#define Dn  1024
#define Hn  16
#define HDn 64
#define Mn  (Bn * Tn)   // 4096

// -------- scratch (static device globals; no allocations allowed) --------
__device__ float g_Q[(size_t)Bn * Hn * Tn * HDn];   // [B,H,T,64]
__device__ float g_K[(size_t)Bn * Hn * Tn * HDn];
__device__ float g_V[(size_t)Bn * Hn * Tn * HDn];
__device__ float g_O[(size_t)Mn * Dn];              // [B*T, D]
__device__ float g_P[(size_t)Mn * Dn];              // pre-LN

// ---------------- tf32 helpers ----------------
__device__ __forceinline__ float tf32f(float x) {
    unsigned u;
    asm("cvt.rna.tf32.f32 %0, %1;" : "=r"(u) : "f"(x));
    return __uint_as_float(u);
}
__device__ __forceinline__ unsigned fu(float x) { return __float_as_uint(x); }

// D += A(16x8, row) * B(8x8, col), tf32 in, f32 out
__device__ __forceinline__ void mma8(float* d, const unsigned* a,
                                     unsigned b0, unsigned b1) {
    asm volatile(
        "mma.sync.aligned.m16n8k8.row.col.f32.tf32.tf32.f32 "
        "{%0,%1,%2,%3},{%4,%5,%6,%7},{%8,%9},{%0,%1,%2,%3};"
        : "+f"(d[0]), "+f"(d[1]), "+f"(d[2]), "+f"(d[3])
        : "r"(a[0]), "r"(a[1]), "r"(a[2]), "r"(a[3]), "r"(b0), "r"(b1));
}

// =========================================================================
// Tensor-core GEMM, 3xTF32, 128x128 CTA tile, Kchunk=32, double-buffered.
// 256 threads = 8 warps (4m x 2n); warp tile 32x64 (2 m-tiles x 8 n-tiles).
// A smem: [128][36] (stride 36 => conflict-free A-frag LDS)
// B smem: [32][136] (stride 136 => conflict-free B-frag LDS)
// mode 0: out = A@W+bias scattered to [B,H,T,64];  mode 1: +resid row-major.
// =========================================================================
#define G_AS 4608            // 128*36
#define G_BS 4352            // 32*136
#define G_BUF (2*G_AS + 2*G_BS)      // 17920 floats
#define GEMM_SMEM_BYTES (2 * G_BUF * 4)  // 143360

__global__ void __launch_bounds__(256) gemm_tc(
    const float* __restrict__ A, const float* __restrict__ W,
    const float* __restrict__ bias, const float* __restrict__ resid,
    float* __restrict__ out, int mode)
{
    extern __shared__ float sm[];
    const int tid = threadIdx.x, lane = tid & 31, w = tid >> 5;
    const int g = lane >> 2, tig = lane & 3;
    const int wm = w & 3, wn = w >> 2;
    const int m0 = blockIdx.y * 128, n0 = blockIdx.x * 128;

    float acc[2][8][4];
#pragma unroll
    for (int mt = 0; mt < 2; mt++)
#pragma unroll
        for (int nt = 0; nt < 8; nt++)
#pragma unroll
            for (int j = 0; j < 4; j++) acc[mt][nt][j] = 0.f;

    // per-thread load slots
    const int ar = tid >> 1;            // unused pattern replaced below
    (void)ar;

    // prologue: load chunk 0 into buffer 0
    {
        float* Ah = sm;           float* Al = sm + G_AS;
        float* Bh = sm + 2*G_AS;  float* Bl = Bh + G_BS;
#pragma unroll
        for (int i = 0; i < 4; i++) {
            int s = tid + i * 256;
            int r = s >> 3, c4 = (s & 7) << 2;
            float4 v = *(const float4*)(A + (size_t)(m0 + r) * Dn + c4);
            float hx = tf32f(v.x), hy = tf32f(v.y), hz = tf32f(v.z), hw = tf32f(v.w);
            *(float4*)(Ah + r * 36 + c4) = make_float4(hx, hy, hz, hw);
            *(float4*)(Al + r * 36 + c4) =
                make_float4(tf32f(v.x - hx), tf32f(v.y - hy), tf32f(v.z - hz), tf32f(v.w - hw));
            int k = s >> 5, n4 = (s & 31) << 2;
            float4 bv = *(const float4*)(W + (size_t)k * Dn + n0 + n4);
            float bx = tf32f(bv.x), by = tf32f(bv.y), bz = tf32f(bv.z), bw = tf32f(bv.w);
            *(float4*)(Bh + k * 136 + n4) = make_float4(bx, by, bz, bw);
            *(float4*)(Bl + k * 136 + n4) =
                make_float4(tf32f(bv.x - bx), tf32f(bv.y - by), tf32f(bv.z - bz), tf32f(bv.w - bw));
        }
    }
    __syncthreads();

    for (int c = 0; c < 32; c++) {
        float* base = sm + (c & 1) * G_BUF;
        float* Ah = base;          float* Al = base + G_AS;
        float* Bh = base + 2*G_AS; float* Bl = Bh + G_BS;

        float4 pa[4], pb[4];
        const bool pf = (c < 31);
        if (pf) {
            int k0n = (c + 1) * 32;
#pragma unroll
            for (int i = 0; i < 4; i++) {
                int s = tid + i * 256;
                int r = s >> 3, c4 = (s & 7) << 2;
                pa[i] = *(const float4*)(A + (size_t)(m0 + r) * Dn + k0n + c4);
                int k = s >> 5, n4 = (s & 31) << 2;
                pb[i] = *(const float4*)(W + (size_t)(k0n + k) * Dn + n0 + n4);
            }
        }

#pragma unroll
        for (int kk = 0; kk < 4; kk++) {
            unsigned ah[2][4], al[2][4];
#pragma unroll
            for (int mt = 0; mt < 2; mt++) {
                int rbm = wm * 32 + mt * 16;
                int bi = (rbm + g) * 36 + kk * 8 + tig;
                ah[mt][0] = fu(Ah[bi]);          al[mt][0] = fu(Al[bi]);
                ah[mt][1] = fu(Ah[bi + 8 * 36]); al[mt][1] = fu(Al[bi + 8 * 36]);
                ah[mt][2] = fu(Ah[bi + 4]);      al[mt][2] = fu(Al[bi + 4]);
                ah[mt][3] = fu(Ah[bi + 8 * 36 + 4]); al[mt][3] = fu(Al[bi + 8 * 36 + 4]);
            }
#pragma unroll
            for (int nt = 0; nt < 8; nt++) {
                int cb = wn * 64 + nt * 8;
                int bb = (kk * 8 + tig) * 136 + cb + g;
                unsigned b0h = fu(Bh[bb]), b1h = fu(Bh[bb + 4 * 136]);
                unsigned b0l = fu(Bl[bb]), b1l = fu(Bl[bb + 4 * 136]);
#pragma unroll
                for (int mt = 0; mt < 2; mt++) {
                    mma8(acc[mt][nt], ah[mt], b0h, b1h);
                    mma8(acc[mt][nt], ah[mt], b0l, b1l);
                    mma8(acc[mt][nt], al[mt], b0h, b1h);
                }
            }
        }

        if (pf) {
            float* nb = sm + ((c + 1) & 1) * G_BUF;
            float* Ah2 = nb;           float* Al2 = nb + G_AS;
            float* Bh2 = nb + 2*G_AS;  float* Bl2 = Bh2 + G_BS;
#pragma unroll
            for (int i = 0; i < 4; i++) {
                int s = tid + i * 256;
                int r = s >> 3, c4 = (s & 7) << 2;
                float4 v = pa[i];
                float hx = tf32f(v.x), hy = tf32f(v.y), hz = tf32f(v.z), hw = tf32f(v.w);
                *(float4*)(Ah2 + r * 36 + c4) = make_float4(hx, hy, hz, hw);
                *(float4*)(Al2 + r * 36 + c4) =
                    make_float4(tf32f(v.x - hx), tf32f(v.y - hy), tf32f(v.z - hz), tf32f(v.w - hw));
                int k = s >> 5, n4 = (s & 31) << 2;
                float4 bv = pb[i];
                float bx = tf32f(bv.x), by = tf32f(bv.y), bz = tf32f(bv.z), bw = tf32f(bv.w);
                *(float4*)(Bh2 + k * 136 + n4) = make_float4(bx, by, bz, bw);
                *(float4*)(Bl2 + k * 136 + n4) =
                    make_float4(tf32f(bv.x - bx), tf32f(bv.y - by), tf32f(bv.z - bz), tf32f(bv.w - bw));
            }
        }
        __syncthreads();
    }

    // epilogue
#pragma unroll
    for (int mt = 0; mt < 2; mt++) {
#pragma unroll
        for (int nt = 0; nt < 8; nt++) {
            int r0 = m0 + wm * 32 + mt * 16 + g;
            int n = n0 + wn * 64 + nt * 8 + 2 * tig;
            float bx = bias[n], by = bias[n + 1];
            if (mode == 0) {
#pragma unroll
                for (int rp = 0; rp < 2; rp++) {
                    int r = r0 + rp * 8;
                    int bb = r >> 11, t = r & (Tn - 1);
                    int h = n >> 6, hd = n & 63;
                    float2 val = make_float2(acc[mt][nt][2 * rp] + bx,
                                             acc[mt][nt][2 * rp + 1] + by);
                    *(float2*)&out[((((size_t)bb * Hn + h) * Tn) + t) * HDn + hd] = val;
                }
            } else {
#pragma unroll
                for (int rp = 0; rp < 2; rp++) {
                    int r = r0 + rp * 8;
                    size_t off = (size_t)r * Dn + n;
                    float2 rv = *(const float2*)&resid[off];
                    float2 val = make_float2(acc[mt][nt][2 * rp] + bx + rv.x,
                                             acc[mt][nt][2 * rp + 1] + by + rv.y);
                    *(float2*)&out[off] = val;
                }
            }
        }
    }
}

// =========================================================================
// Tensor-core flash attention. CTA = (bh, 128-query tile), 8 warps,
// each warp owns 16 query rows. Key tiles of 64, double-buffered.
// QK^T in 3xTF32; PV single tf32. Online softmax, O in registers.
// smem: Qraw[128][68] | Ps[128][68] | 2 x { Kh[64][68], Kl[64][68], Vs[64][72] }
// =========================================================================
#define A_QRAW (128 * 68)        // 8704
#define A_PS   (128 * 68)        // 8704
#define A_KS   (64 * 68)         // 4352
#define A_VS   (64 * 72)         // 4608
#define A_BUF  (2 * A_KS + A_VS) // 13312
#define ATT_SMEM_BYTES ((A_QRAW + A_PS + 2 * A_BUF) * 4)  // 176128

__global__ void __launch_bounds__(256) attn_tc(
    const float* __restrict__ gQ, const float* __restrict__ gK,
    const float* __restrict__ gV, float* __restrict__ gO)
{
    extern __shared__ float sm[];
    float* Qraw = sm;
    float* Ps = sm + A_QRAW;
    float* bufbase = sm + A_QRAW + A_PS;

    const int tid = threadIdx.x, lane = tid & 31, w = tid >> 5;
    const int g = lane >> 2, tig = lane & 3;
    const int bh = blockIdx.y;
    const int q0 = blockIdx.x << 7;
    const int b = bh >> 4, h = bh & 15;
    const int rb = w * 16;

    const float* Q = gQ + ((size_t)bh * Tn + q0) * HDn;
    const float* K = gK + (size_t)bh * Tn * HDn;
    const float* V = gV + (size_t)bh * Tn * HDn;

    // stage Q (scaled by 1/8)
#pragma unroll
    for (int i = 0; i < 8; i++) {
        int s = tid + i * 256;
        int r = s >> 4, c4 = (s & 15) << 2;
        float4 v = *(const float4*)&Q[r * 64 + c4];
        *(float4*)&Qraw[r * 68 + c4] =
            make_float4(v.x * 0.125f, v.y * 0.125f, v.z * 0.125f, v.w * 0.125f);
    }
    // load K/V tile 0 into buf 0
    {
        float* Kh = bufbase; float* Kl = Kh + A_KS; float* Vs = Kh + 2 * A_KS;
#pragma unroll
        for (int i = 0; i < 4; i++) {
            int s = tid + i * 256;
            int r = s >> 4, c4 = (s & 15) << 2;
            float4 kv = *(const float4*)&K[r * 64 + c4];
            float hx = tf32f(kv.x), hy = tf32f(kv.y), hz = tf32f(kv.z), hw = tf32f(kv.w);
            *(float4*)&Kh[r * 68 + c4] = make_float4(hx, hy, hz, hw);
            *(float4*)&Kl[r * 68 + c4] =
                make_float4(tf32f(kv.x - hx), tf32f(kv.y - hy), tf32f(kv.z - hz), tf32f(kv.w - hw));
            float4 vv = *(const float4*)&V[r * 64 + c4];
            *(float4*)&Vs[r * 72 + c4] =
                make_float4(tf32f(vv.x), tf32f(vv.y), tf32f(vv.z), tf32f(vv.w));
        }
    }
    __syncthreads();

    // Q fragments (hi/lo) in registers
    unsigned qh[8][4], ql[8][4];
#pragma unroll
    for (int kk = 0; kk < 8; kk++) {
        int bi = (rb + g) * 68 + kk * 8 + tig;
        float x0 = Qraw[bi], x1 = Qraw[bi + 8 * 68];
        float x2 = Qraw[bi + 4], x3 = Qraw[bi + 8 * 68 + 4];
        float h0 = tf32f(x0), h1 = tf32f(x1), h2 = tf32f(x2), h3 = tf32f(x3);
        qh[kk][0] = fu(h0); qh[kk][1] = fu(h1); qh[kk][2] = fu(h2); qh[kk][3] = fu(h3);
        ql[kk][0] = fu(tf32f(x0 - h0)); ql[kk][1] = fu(tf32f(x1 - h1));
        ql[kk][2] = fu(tf32f(x2 - h2)); ql[kk][3] = fu(tf32f(x3 - h3));
    }

    float oacc[8][4];
#pragma unroll
    for (int nt = 0; nt < 8; nt++)
#pragma unroll
        for (int j = 0; j < 4; j++) oacc[nt][j] = 0.f;
    float mst0 = -1e30f, mst1 = -1e30f, lst0 = 0.f, lst1 = 0.f;

    for (int it = 0; it < Tn / 64; it++) {
        float* Kh = bufbase + (it & 1) * A_BUF;
        float* Kl = Kh + A_KS;
        float* Vs = Kh + 2 * A_KS;
        float* nKh = bufbase + ((it + 1) & 1) * A_BUF;
        float* nKl = nKh + A_KS;
        float* nVs = nKh + 2 * A_KS;
        const bool pf = (it < Tn / 64 - 1);
        const int ktn = (it + 1) << 6;

        float4 pk[4];
        if (pf) {
#pragma unroll
            for (int i = 0; i < 4; i++) {
                int s = tid + i * 256;
                int r = s >> 4, c4 = (s & 15) << 2;
                pk[i] = *(const float4*)&K[(ktn + r) * 64 + c4];
            }
        }

        // ---- S = Q K^T (3xTF32) ----
        float sacc[8][4];
#pragma unroll
        for (int nt = 0; nt < 8; nt++)
#pragma unroll
            for (int j = 0; j < 4; j++) sacc[nt][j] = 0.f;

#pragma unroll
        for (int kk = 0; kk < 8; kk++) {
#pragma unroll
            for (int nt = 0; nt < 8; nt++) {
                int bi = (nt * 8 + g) * 68 + kk * 8 + tig;
                unsigned b0h = fu(Kh[bi]), b1h = fu(Kh[bi + 4]);
                unsigned b0l = fu(Kl[bi]), b1l = fu(Kl[bi + 4]);
                mma8(sacc[nt], qh[kk], b0h, b1h);
                mma8(sacc[nt], qh[kk], b0l, b1l);
                mma8(sacc[nt], ql[kk], b0h, b1h);
            }
        }

        // store prefetched K, issue V prefetch
        float4 pv[4];
        if (pf) {
#pragma unroll
            for (int i = 0; i < 4; i++) {
                int s = tid + i * 256;
                int r = s >> 4, c4 = (s & 15) << 2;
                float4 kv = pk[i];
                float hx = tf32f(kv.x), hy = tf32f(kv.y), hz = tf32f(kv.z), hw = tf32f(kv.w);
                *(float4*)&nKh[r * 68 + c4] = make_float4(hx, hy, hz, hw);
                *(float4*)&nKl[r * 68 + c4] =
                    make_float4(tf32f(kv.x - hx), tf32f(kv.y - hy), tf32f(kv.z - hz), tf32f(kv.w - hw));
                pv[i] = *(const float4*)&V[(ktn + r) * 64 + c4];
            }
        }

        // ---- online softmax ----
        float mx0 = -1e30f, mx1 = -1e30f;
#pragma unroll
        for (int nt = 0; nt < 8; nt++) {
            mx0 = fmaxf(mx0, fmaxf(sacc[nt][0], sacc[nt][1]));
            mx1 = fmaxf(mx1, fmaxf(sacc[nt][2], sacc[nt][3]));
        }
        mx0 = fmaxf(mx0, __shfl_xor_sync(0xffffffffu, mx0, 1));
        mx0 = fmaxf(mx0, __shfl_xor_sync(0xffffffffu, mx0, 2));
        mx1 = fmaxf(mx1, __shfl_xor_sync(0xffffffffu, mx1, 1));
        mx1 = fmaxf(mx1, __shfl_xor_sync(0xffffffffu, mx1, 2));
        float mn0 = fmaxf(mst0, mx0), mn1 = fmaxf(mst1, mx1);
        float c0 = __expf(mst0 - mn0), c1 = __expf(mst1 - mn1);
        mst0 = mn0; mst1 = mn1;
        float s0 = 0.f, s1 = 0.f;
#pragma unroll
        for (int nt = 0; nt < 8; nt++) {
            float p0 = tf32f(__expf(sacc[nt][0] - mn0));
            float p1 = tf32f(__expf(sacc[nt][1] - mn0));
            float p2 = tf32f(__expf(sacc[nt][2] - mn1));
            float p3 = tf32f(__expf(sacc[nt][3] - mn1));
            s0 += p0 + p1; s1 += p2 + p3;
            sacc[nt][0] = p0; sacc[nt][1] = p1; sacc[nt][2] = p2; sacc[nt][3] = p3;
            oacc[nt][0] *= c0; oacc[nt][1] *= c0; oacc[nt][2] *= c1; oacc[nt][3] *= c1;
        }
        s0 += __shfl_xor_sync(0xffffffffu, s0, 1);
        s0 += __shfl_xor_sync(0xffffffffu, s0, 2);
        s1 += __shfl_xor_sync(0xffffffffu, s1, 1);
        s1 += __shfl_xor_sync(0xffffffffu, s1, 2);
        lst0 = lst0 * c0 + s0;
        lst1 = lst1 * c1 + s1;

        // write P tile (own warp rows only)
#pragma unroll
        for (int nt = 0; nt < 8; nt++) {
            *(float2*)&Ps[(rb + g) * 68 + nt * 8 + 2 * tig] =
                make_float2(sacc[nt][0], sacc[nt][1]);
            *(float2*)&Ps[(rb + g + 8) * 68 + nt * 8 + 2 * tig] =
                make_float2(sacc[nt][2], sacc[nt][3]);
        }
        __syncwarp();

        // ---- O += P V ----
#pragma unroll
        for (int kk = 0; kk < 8; kk++) {
            int ai = (rb + g) * 68 + kk * 8 + tig;
            unsigned a[4] = { fu(Ps[ai]), fu(Ps[ai + 8 * 68]),
                              fu(Ps[ai + 4]), fu(Ps[ai + 8 * 68 + 4]) };
#pragma unroll
            for (int nt = 0; nt < 8; nt++) {
                int bi = (kk * 8 + tig) * 72 + nt * 8 + g;
                mma8(oacc[nt], a, fu(Vs[bi]), fu(Vs[bi + 4 * 72]));
            }
        }

        if (pf) {
#pragma unroll
            for (int i = 0; i < 4; i++) {
                int s = tid + i * 256;
                int r = s >> 4, c4 = (s & 15) << 2;
                float4 vv = pv[i];
                *(float4*)&nVs[r * 72 + c4] =
                    make_float4(tf32f(vv.x), tf32f(vv.y), tf32f(vv.z), tf32f(vv.w));
            }
        }
        __syncthreads();
    }

    // epilogue
    float i0 = 1.f / lst0, i1 = 1.f / lst1;
    int gr0 = b * Tn + q0 + rb + g;
#pragma unroll
    for (int nt = 0; nt < 8; nt++) {
        int col = h * HDn + nt * 8 + 2 * tig;
        *(float2*)&gO[(size_t)gr0 * Dn + col] =
            make_float2(oacc[nt][0] * i0, oacc[nt][1] * i0);
        *(float2*)&gO[(size_t)(gr0 + 8) * Dn + col] =
            make_float2(oacc[nt][2] * i1, oacc[nt][3] * i1);
    }
}

// =========================================================================
// LayerNorm: 1 block per row, 256 threads, 1 float4 per thread.
// =========================================================================
__global__ void __launch_bounds__(256) ln_kernel(
    const float* __restrict__ P, const float* __restrict__ gw,
    const float* __restrict__ gb, float* __restrict__ out)
{
    const int row = blockIdx.x;
    const int tid = threadIdx.x;
    const float4 v = ((const float4*)(P + (size_t)row * Dn))[tid];

    float s  = v.x + v.y + v.z + v.w;
    float ss = v.x * v.x + v.y * v.y + v.z * v.z + v.w * v.w;
#pragma unroll
    for (int off = 16; off; off >>= 1) {
        s  += __shfl_xor_sync(0xffffffffu, s, off);
        ss += __shfl_xor_sync(0xffffffffu, ss, off);
    }
    __shared__ float sh_s[8], sh_ss[8];
    const int w = tid >> 5, lane = tid & 31;
    if (lane == 0) { sh_s[w] = s; sh_ss[w] = ss; }
    __syncthreads();
    if (w == 0) {
        float s2  = (lane < 8) ? sh_s[lane]  : 0.f;
        float ss2 = (lane < 8) ? sh_ss[lane] : 0.f;
#pragma unroll
        for (int off = 4; off; off >>= 1) {
            s2  += __shfl_xor_sync(0xffffffffu, s2, off);
            ss2 += __shfl_xor_sync(0xffffffffu, ss2, off);
        }
        if (lane == 0) { sh_s[0] = s2; sh_ss[0] = ss2; }
    }
    __syncthreads();

    const float mu  = sh_s[0] * (1.0f / Dn);
    const float var = sh_ss[0] * (1.0f / Dn) - mu * mu;
    const float rs  = rsqrtf(var + 1e-5f);

    const float4 g = ((const float4*)gw)[tid];
    const float4 bb = ((const float4*)gb)[tid];
    float4 r;
    r.x = (v.x - mu) * rs * g.x + bb.x;
    r.y = (v.y - mu) * rs * g.y + bb.y;
    r.z = (v.z - mu) * rs * g.z + bb.z;
    r.w = (v.w - mu) * rs * g.w + bb.w;
    ((float4*)(out + (size_t)row * Dn))[tid] = r;
}

// =========================================================================
extern "C" void kernel_launch(void* const* d_in, const int* in_sizes, int n_in,
                              void* d_out, int out_size)
{
    const float* x  = (const float*)d_in[0];
    const float* Wq = (const float*)d_in[1];
    const float* bq = (const float*)d_in[2];
    const float* Wk = (const float*)d_in[3];
    const float* bk = (const float*)d_in[4];
    const float* Wv = (const float*)d_in[5];
    const float* bv = (const float*)d_in[6];
    const float* Wo = (const float*)d_in[7];
    const float* bo = (const float*)d_in[8];
    const float* lg = (const float*)d_in[9];
    const float* lb = (const float*)d_in[10];
    float* out = (float*)d_out;

    float *gQ, *gK, *gV, *gO, *gP;
    cudaGetSymbolAddress((void**)&gQ, g_Q);
    cudaGetSymbolAddress((void**)&gK, g_K);
    cudaGetSymbolAddress((void**)&gV, g_V);
    cudaGetSymbolAddress((void**)&gO, g_O);
    cudaGetSymbolAddress((void**)&gP, g_P);

    cudaFuncSetAttribute(gemm_tc, cudaFuncAttributeMaxDynamicSharedMemorySize,
                         GEMM_SMEM_BYTES);
    cudaFuncSetAttribute(attn_tc, cudaFuncAttributeMaxDynamicSharedMemorySize,
                         ATT_SMEM_BYTES);

    dim3 gproj(Dn / 128, Mn / 128);   // (8, 32)
    gemm_tc<<<gproj, 256, GEMM_SMEM_BYTES>>>(x, Wq, bq, nullptr, gQ, 0);
    gemm_tc<<<gproj, 256, GEMM_SMEM_BYTES>>>(x, Wk, bk, nullptr, gK, 0);
    gemm_tc<<<gproj, 256, GEMM_SMEM_BYTES>>>(x, Wv, bv, nullptr, gV, 0);

    attn_tc<<<dim3(Tn / 128, Bn * Hn), 256, ATT_SMEM_BYTES>>>(gQ, gK, gV, gO);

    gemm_tc<<<gproj, 256, GEMM_SMEM_BYTES>>>(gO, Wo, bo, x, gP, 1);

    ln_kernel<<<Mn, 256>>>(gP, lg, lb, out);
}

// round 3
// speedup vs baseline: 3.5902x; 2.1414x over previous
#include <cuda_runtime.h>
#include <math.h>
#include <stdint.h>

#define Bn  2
#define Tn  2048
#define Dn  1024
#define Hn  16
#define HDn 64
#define Mn  (Bn * Tn)   // 4096

// -------- scratch (static device globals; no allocations allowed) --------
__device__ float g_Q[(size_t)Bn * Hn * Tn * HDn];   // [B,H,T,64]
__device__ float g_K[(size_t)Bn * Hn * Tn * HDn];
__device__ float g_V[(size_t)Bn * Hn * Tn * HDn];
__device__ float g_O[(size_t)Mn * Dn];              // [B*T, D]
__device__ float g_P[(size_t)Mn * Dn];              // pre-LN

// ---------------- helpers ----------------
__device__ __forceinline__ unsigned fu(float x) { return __float_as_uint(x); }

// D += A(16x8, row) * B(8x8, col), tf32 in (HW-truncated fp32), f32 out
__device__ __forceinline__ void mma8(float* d, const unsigned* a,
                                     unsigned b0, unsigned b1) {
    asm volatile(
        "mma.sync.aligned.m16n8k8.row.col.f32.tf32.tf32.f32 "
        "{%0,%1,%2,%3},{%4,%5,%6,%7},{%8,%9},{%0,%1,%2,%3};"
        : "+f"(d[0]), "+f"(d[1]), "+f"(d[2]), "+f"(d[3])
        : "r"(a[0]), "r"(a[1]), "r"(a[2]), "r"(a[3]), "r"(b0), "r"(b1));
}

__device__ __forceinline__ void cpa16(float* dst_smem, const float* src) {
    unsigned d = (unsigned)__cvta_generic_to_shared(dst_smem);
    asm volatile("cp.async.cg.shared.global [%0], [%1], 16;" :: "r"(d), "l"(src));
}
__device__ __forceinline__ void cp_commit() {
    asm volatile("cp.async.commit_group;");
}
template<int N> __device__ __forceinline__ void cp_wait() {
    asm volatile("cp.async.wait_group %0;" :: "n"(N));
}

// =========================================================================
// Tensor-core GEMM, single-pass tf32, 128x128 CTA tile, Kchunk=32,
// cp.async double-buffered. 256 threads = 8 warps (4m x 2n).
// A smem [128][36] (stride 36 -> conflict-free A-frag LDS)
// B smem [32][136] (stride 136 -> conflict-free B-frag LDS)
// =========================================================================
#define G_AS (128 * 36)      // 4608
#define G_BS (32 * 136)      // 4352
#define G_BUF (G_AS + G_BS)  // 8960 floats
#define GEMM_SMEM_BYTES (2 * G_BUF * 4)  // 71680

__device__ __forceinline__ void gemm_issue(
    float* buf, const float* A, const float* W, int m0, int n0, int k0, int tid)
{
    float* As = buf;
    float* Bs = buf + G_AS;
#pragma unroll
    for (int i = 0; i < 4; i++) {
        int s = tid + i * 256;
        int r = s >> 3, c4 = (s & 7) << 2;
        cpa16(As + r * 36 + c4, A + (size_t)(m0 + r) * Dn + k0 + c4);
        int k = s >> 5, n4 = (s & 31) << 2;
        cpa16(Bs + k * 136 + n4, W + (size_t)(k0 + k) * Dn + n0 + n4);
    }
    cp_commit();
}

__device__ __forceinline__ void gemm_main(
    const float* __restrict__ A, const float* __restrict__ W,
    const float* __restrict__ bias, const float* __restrict__ resid,
    float* __restrict__ out, int mode, float* sm)
{
    const int tid = threadIdx.x, lane = tid & 31, w = tid >> 5;
    const int g = lane >> 2, tig = lane & 3;
    const int wm = w & 3, wn = w >> 2;
    const int m0 = blockIdx.y * 128, n0 = blockIdx.x * 128;

    float acc[2][8][4];
#pragma unroll
    for (int mt = 0; mt < 2; mt++)
#pragma unroll
        for (int nt = 0; nt < 8; nt++)
#pragma unroll
            for (int j = 0; j < 4; j++) acc[mt][nt][j] = 0.f;

    gemm_issue(sm, A, W, m0, n0, 0, tid);
    gemm_issue(sm + G_BUF, A, W, m0, n0, 32, tid);

    for (int c = 0; c < 32; c++) {
        if (c < 31) cp_wait<1>(); else cp_wait<0>();
        __syncthreads();
        float* As = sm + (c & 1) * G_BUF;
        float* Bs = As + G_AS;

#pragma unroll
        for (int kk = 0; kk < 4; kk++) {
            unsigned ah[2][4];
#pragma unroll
            for (int mt = 0; mt < 2; mt++) {
                int bi = (wm * 32 + mt * 16 + g) * 36 + kk * 8 + tig;
                ah[mt][0] = fu(As[bi]);
                ah[mt][1] = fu(As[bi + 8 * 36]);
                ah[mt][2] = fu(As[bi + 4]);
                ah[mt][3] = fu(As[bi + 8 * 36 + 4]);
            }
#pragma unroll
            for (int nt = 0; nt < 8; nt++) {
                int bb = (kk * 8 + tig) * 136 + wn * 64 + nt * 8 + g;
                unsigned b0 = fu(Bs[bb]), b1 = fu(Bs[bb + 4 * 136]);
                mma8(acc[0][nt], ah[0], b0, b1);
                mma8(acc[1][nt], ah[1], b0, b1);
            }
        }
        __syncthreads();
        if (c + 2 < 32)
            gemm_issue(sm + (c & 1) * G_BUF, A, W, m0, n0, (c + 2) * 32, tid);
    }

    // epilogue
#pragma unroll
    for (int mt = 0; mt < 2; mt++) {
#pragma unroll
        for (int nt = 0; nt < 8; nt++) {
            int r0 = m0 + wm * 32 + mt * 16 + g;
            int n = n0 + wn * 64 + nt * 8 + 2 * tig;
            float bx = bias[n], by = bias[n + 1];
            if (mode == 0) {
#pragma unroll
                for (int rp = 0; rp < 2; rp++) {
                    int r = r0 + rp * 8;
                    int bb = r >> 11, t = r & (Tn - 1);
                    int h = n >> 6, hd = n & 63;
                    float2 val = make_float2(acc[mt][nt][2 * rp] + bx,
                                             acc[mt][nt][2 * rp + 1] + by);
                    *(float2*)&out[((((size_t)bb * Hn + h) * Tn) + t) * HDn + hd] = val;
                }
            } else {
#pragma unroll
                for (int rp = 0; rp < 2; rp++) {
                    int r = r0 + rp * 8;
                    size_t off = (size_t)r * Dn + n;
                    float2 rv = *(const float2*)&resid[off];
                    float2 val = make_float2(acc[mt][nt][2 * rp] + bx + rv.x,
                                             acc[mt][nt][2 * rp + 1] + by + rv.y);
                    *(float2*)&out[off] = val;
                }
            }
        }
    }
}

__global__ void __launch_bounds__(256, 2) qkv_gemm(
    const float* __restrict__ x,
    const float* __restrict__ Wq, const float* __restrict__ bq,
    const float* __restrict__ Wk, const float* __restrict__ bk,
    const float* __restrict__ Wv, const float* __restrict__ bv,
    float* __restrict__ gQ, float* __restrict__ gK, float* __restrict__ gV)
{
    extern __shared__ float sm[];
    const float* W; const float* b; float* o;
    if (blockIdx.z == 0)      { W = Wq; b = bq; o = gQ; }
    else if (blockIdx.z == 1) { W = Wk; b = bk; o = gK; }
    else                      { W = Wv; b = bv; o = gV; }
    gemm_main(x, W, b, nullptr, o, 0, sm);
}

__global__ void __launch_bounds__(256, 2) oproj_gemm(
    const float* __restrict__ A, const float* __restrict__ W,
    const float* __restrict__ b, const float* __restrict__ resid,
    float* __restrict__ out)
{
    extern __shared__ float sm[];
    gemm_main(A, W, b, resid, out, 1, sm);
}

// =========================================================================
// Tensor-core flash attention, single-pass tf32, cp.async double-buffered.
// CTA = (bh, 128-query tile), 8 warps x 16 query rows. K-tiles of 64.
// smem: Q[128][68] (reused as P after frag extraction) |
//       2 x { K[64][68], V[64][72] }  = 106496 bytes.
// =========================================================================
#define A_KS  (64 * 68)          // 4352
#define A_VS  (64 * 72)          // 4608
#define A_BUF (A_KS + A_VS)      // 8960
#define A_QS  (128 * 68)         // 8704
#define ATT_SMEM_BYTES ((A_QS + 2 * A_BUF) * 4)  // 106496

__device__ __forceinline__ void attn_issue(
    float* stage, const float* K, const float* V, int kt, int tid)
{
    float* Ks = stage;
    float* Vs = stage + A_KS;
#pragma unroll
    for (int i = 0; i < 4; i++) {
        int s = tid + i * 256;
        int r = s >> 4, c4 = (s & 15) << 2;
        cpa16(Ks + r * 68 + c4, K + (size_t)(kt + r) * HDn + c4);
        cpa16(Vs + r * 72 + c4, V + (size_t)(kt + r) * HDn + c4);
    }
    cp_commit();
}

__global__ void __launch_bounds__(256, 2) attn_tc(
    const float* __restrict__ gQ, const float* __restrict__ gK,
    const float* __restrict__ gV, float* __restrict__ gO)
{
    extern __shared__ float sm[];
    float* Qs = sm;                 // reused as Ps after frag extraction
    float* bufs = sm + A_QS;

    const int tid = threadIdx.x, lane = tid & 31, w = tid >> 5;
    const int g = lane >> 2, tig = lane & 3;
    const int bh = blockIdx.y;
    const int q0 = blockIdx.x << 7;
    const int b = bh >> 4, h = bh & 15;
    const int rb = w * 16;

    const float* Q = gQ + ((size_t)bh * Tn + q0) * HDn;
    const float* K = gK + (size_t)bh * Tn * HDn;
    const float* V = gV + (size_t)bh * Tn * HDn;

    // group 0: Q + KV tile 0
#pragma unroll
    for (int i = 0; i < 8; i++) {
        int s = tid + i * 256;
        int r = s >> 4, c4 = (s & 15) << 2;
        cpa16(Qs + r * 68 + c4, Q + (size_t)r * HDn + c4);
    }
    {
        float* Ks = bufs;
        float* Vs = bufs + A_KS;
#pragma unroll
        for (int i = 0; i < 4; i++) {
            int s = tid + i * 256;
            int r = s >> 4, c4 = (s & 15) << 2;
            cpa16(Ks + r * 68 + c4, K + (size_t)r * HDn + c4);
            cpa16(Vs + r * 72 + c4, V + (size_t)r * HDn + c4);
        }
    }
    cp_commit();
    attn_issue(bufs + A_BUF, K, V, 64, tid);     // group 1: KV tile 1

    cp_wait<1>();
    __syncthreads();

    // extract Q fragments, fold 1/sqrt(64)
    unsigned qh[8][4];
#pragma unroll
    for (int kk = 0; kk < 8; kk++) {
        int bi = (rb + g) * 68 + kk * 8 + tig;
        qh[kk][0] = fu(Qs[bi] * 0.125f);
        qh[kk][1] = fu(Qs[bi + 8 * 68] * 0.125f);
        qh[kk][2] = fu(Qs[bi + 4] * 0.125f);
        qh[kk][3] = fu(Qs[bi + 8 * 68 + 4] * 0.125f);
    }
    __syncthreads();           // Qs now free -> Ps
    float* Ps = Qs;

    float oacc[8][4];
#pragma unroll
    for (int nt = 0; nt < 8; nt++)
#pragma unroll
        for (int j = 0; j < 4; j++) oacc[nt][j] = 0.f;
    float mst0 = -1e30f, mst1 = -1e30f, lst0 = 0.f, lst1 = 0.f;

    for (int it = 0; it < 32; it++) {
        if (it > 0) {
            if (it < 31) cp_wait<1>(); else cp_wait<0>();
            __syncthreads();
        }
        float* Ks = bufs + (it & 1) * A_BUF;
        float* Vs = Ks + A_KS;

        // ---- S = Q K^T ----
        float sacc[8][4];
#pragma unroll
        for (int nt = 0; nt < 8; nt++)
#pragma unroll
            for (int j = 0; j < 4; j++) sacc[nt][j] = 0.f;

#pragma unroll
        for (int kk = 0; kk < 8; kk++) {
#pragma unroll
            for (int nt = 0; nt < 8; nt++) {
                int bi = (nt * 8 + g) * 68 + kk * 8 + tig;
                mma8(sacc[nt], qh[kk], fu(Ks[bi]), fu(Ks[bi + 4]));
            }
        }

        // ---- online softmax (row quads: lanes xor 1,2) ----
        float mx0 = -1e30f, mx1 = -1e30f;
#pragma unroll
        for (int nt = 0; nt < 8; nt++) {
            mx0 = fmaxf(mx0, fmaxf(sacc[nt][0], sacc[nt][1]));
            mx1 = fmaxf(mx1, fmaxf(sacc[nt][2], sacc[nt][3]));
        }
        mx0 = fmaxf(mx0, __shfl_xor_sync(0xffffffffu, mx0, 1));
        mx0 = fmaxf(mx0, __shfl_xor_sync(0xffffffffu, mx0, 2));
        mx1 = fmaxf(mx1, __shfl_xor_sync(0xffffffffu, mx1, 1));
        mx1 = fmaxf(mx1, __shfl_xor_sync(0xffffffffu, mx1, 2));
        float mn0 = fmaxf(mst0, mx0), mn1 = fmaxf(mst1, mx1);
        float c0 = __expf(mst0 - mn0), c1 = __expf(mst1 - mn1);
        mst0 = mn0; mst1 = mn1;
        float s0 = 0.f, s1 = 0.f;
#pragma unroll
        for (int nt = 0; nt < 8; nt++) {
            float p0 = __expf(sacc[nt][0] - mn0);
            float p1 = __expf(sacc[nt][1] - mn0);
            float p2 = __expf(sacc[nt][2] - mn1);
            float p3 = __expf(sacc[nt][3] - mn1);
            s0 += p0 + p1; s1 += p2 + p3;
            sacc[nt][0] = p0; sacc[nt][1] = p1; sacc[nt][2] = p2; sacc[nt][3] = p3;
            oacc[nt][0] *= c0; oacc[nt][1] *= c0; oacc[nt][2] *= c1; oacc[nt][3] *= c1;
        }
        s0 += __shfl_xor_sync(0xffffffffu, s0, 1);
        s0 += __shfl_xor_sync(0xffffffffu, s0, 2);
        s1 += __shfl_xor_sync(0xffffffffu, s1, 1);
        s1 += __shfl_xor_sync(0xffffffffu, s1, 2);
        lst0 = lst0 * c0 + s0;
        lst1 = lst1 * c1 + s1;

        // write P tile (own warp rows)
#pragma unroll
        for (int nt = 0; nt < 8; nt++) {
            *(float2*)&Ps[(rb + g) * 68 + nt * 8 + 2 * tig] =
                make_float2(sacc[nt][0], sacc[nt][1]);
            *(float2*)&Ps[(rb + g + 8) * 68 + nt * 8 + 2 * tig] =
                make_float2(sacc[nt][2], sacc[nt][3]);
        }
        __syncwarp();

        // ---- O += P V ----
#pragma unroll
        for (int kk = 0; kk < 8; kk++) {
            int ai = (rb + g) * 68 + kk * 8 + tig;
            unsigned a[4] = { fu(Ps[ai]), fu(Ps[ai + 8 * 68]),
                              fu(Ps[ai + 4]), fu(Ps[ai + 8 * 68 + 4]) };
#pragma unroll
            for (int nt = 0; nt < 8; nt++) {
                int bi = (kk * 8 + tig) * 72 + nt * 8 + g;
                mma8(oacc[nt], a, fu(Vs[bi]), fu(Vs[bi + 4 * 72]));
            }
        }
        __syncthreads();
        if (it + 2 < 32)
            attn_issue(bufs + (it & 1) * A_BUF, K, V, (it + 2) << 6, tid);
    }

    // epilogue
    float i0 = 1.f / lst0, i1 = 1.f / lst1;
    int gr0 = b * Tn + q0 + rb + g;
#pragma unroll
    for (int nt = 0; nt < 8; nt++) {
        int col = h * HDn + nt * 8 + 2 * tig;
        *(float2*)&gO[(size_t)gr0 * Dn + col] =
            make_float2(oacc[nt][0] * i0, oacc[nt][1] * i0);
        *(float2*)&gO[(size_t)(gr0 + 8) * Dn + col] =
            make_float2(oacc[nt][2] * i1, oacc[nt][3] * i1);
    }
}

// =========================================================================
// LayerNorm: 1 block per row, 256 threads, 1 float4 per thread.
// =========================================================================
__global__ void __launch_bounds__(256) ln_kernel(
    const float* __restrict__ P, const float* __restrict__ gw,
    const float* __restrict__ gb, float* __restrict__ out)
{
    const int row = blockIdx.x;
    const int tid = threadIdx.x;
    const float4 v = ((const float4*)(P + (size_t)row * Dn))[tid];

    float s  = v.x + v.y + v.z + v.w;
    float ss = v.x * v.x + v.y * v.y + v.z * v.z + v.w * v.w;
#pragma unroll
    for (int off = 16; off; off >>= 1) {
        s  += __shfl_xor_sync(0xffffffffu, s, off);
        ss += __shfl_xor_sync(0xffffffffu, ss, off);
    }
    __shared__ float sh_s[8], sh_ss[8];
    const int w = tid >> 5, lane = tid & 31;
    if (lane == 0) { sh_s[w] = s; sh_ss[w] = ss; }
    __syncthreads();
    if (w == 0) {
        float s2  = (lane < 8) ? sh_s[lane]  : 0.f;
        float ss2 = (lane < 8) ? sh_ss[lane] : 0.f;
#pragma unroll
        for (int off = 4; off; off >>= 1) {
            s2  += __shfl_xor_sync(0xffffffffu, s2, off);
            ss2 += __shfl_xor_sync(0xffffffffu, ss2, off);
        }
        if (lane == 0) { sh_s[0] = s2; sh_ss[0] = ss2; }
    }
    __syncthreads();

    const float mu  = sh_s[0] * (1.0f / Dn);
    const float var = sh_ss[0] * (1.0f / Dn) - mu * mu;
    const float rs  = rsqrtf(var + 1e-5f);

    const float4 g = ((const float4*)gw)[tid];
    const float4 bb = ((const float4*)gb)[tid];
    float4 r;
    r.x = (v.x - mu) * rs * g.x + bb.x;
    r.y = (v.y - mu) * rs * g.y + bb.y;
    r.z = (v.z - mu) * rs * g.z + bb.z;
    r.w = (v.w - mu) * rs * g.w + bb.w;
    ((float4*)(out + (size_t)row * Dn))[tid] = r;
}

// =========================================================================
extern "C" void kernel_launch(void* const* d_in, const int* in_sizes, int n_in,
                              void* d_out, int out_size)
{
    const float* x  = (const float*)d_in[0];
    const float* Wq = (const float*)d_in[1];
    const float* bq = (const float*)d_in[2];
    const float* Wk = (const float*)d_in[3];
    const float* bk = (const float*)d_in[4];
    const float* Wv = (const float*)d_in[5];
    const float* bv = (const float*)d_in[6];
    const float* Wo = (const float*)d_in[7];
    const float* bo = (const float*)d_in[8];
    const float* lg = (const float*)d_in[9];
    const float* lb = (const float*)d_in[10];
    float* out = (float*)d_out;

    float *gQ, *gK, *gV, *gO, *gP;
    cudaGetSymbolAddress((void**)&gQ, g_Q);
    cudaGetSymbolAddress((void**)&gK, g_K);
    cudaGetSymbolAddress((void**)&gV, g_V);
    cudaGetSymbolAddress((void**)&gO, g_O);
    cudaGetSymbolAddress((void**)&gP, g_P);

    cudaFuncSetAttribute(qkv_gemm, cudaFuncAttributeMaxDynamicSharedMemorySize,
                         GEMM_SMEM_BYTES);
    cudaFuncSetAttribute(oproj_gemm, cudaFuncAttributeMaxDynamicSharedMemorySize,
                         GEMM_SMEM_BYTES);
    cudaFuncSetAttribute(attn_tc, cudaFuncAttributeMaxDynamicSharedMemorySize,
                         ATT_SMEM_BYTES);

    qkv_gemm<<<dim3(Dn / 128, Mn / 128, 3), 256, GEMM_SMEM_BYTES>>>(
        x, Wq, bq, Wk, bk, Wv, bv, gQ, gK, gV);

    attn_tc<<<dim3(Tn / 128, Bn * Hn), 256, ATT_SMEM_BYTES>>>(gQ, gK, gV, gO);

    oproj_gemm<<<dim3(Dn / 128, Mn / 128), 256, GEMM_SMEM_BYTES>>>(gO, Wo, bo, x, gP);

    ln_kernel<<<Mn, 256>>>(gP, lg, lb, out);
}